// round 9
// baseline (speedup 1.0000x reference)
#include <cuda_runtime.h>
#include <math.h>

#define Xd 32
#define Yd 16
#define Nn 8192          // 32*16*16
#define Cc 4
#define NITER 5
#define ALPHA 5.0f
#define BETA  5.0f
#define GAMMA 5.0f
#define DEG 7
#define RK 36            // #(i,j), i+j<=7
#define NBLK (RK * Cc + Cc)   // 148 co-resident blocks
#define SMEM_FLOATS (2 * Nn + 160)
#define SMEM_BYTES (SMEM_FLOATS * 4)

// ---- static device scratch ----
__device__ float g_phi[RK][Nn];      // immutable after phase A
__device__ float g_e[Nn];
__device__ float g_pre1[Nn];
__device__ float g_pre2[Nn];
__device__ float g_part[NBLK][Nn];
__device__ float g_q[2][Cc][Nn];
__device__ unsigned g_arr[NBLK];
__device__ unsigned g_gen;

// ---- observer grid barrier (proven) ----
__device__ __forceinline__ void gbar(unsigned tgt, int b, int tid) {
    __syncthreads();
    if (b == 0) {
        if (tid == 0) { __threadfence(); *(volatile unsigned*)&g_arr[0] = tgt; }
        if (tid < NBLK) { while (*(volatile unsigned*)&g_arr[tid] < tgt) { } }
        __syncthreads();
        if (tid == 0) { __threadfence(); *(volatile unsigned*)&g_gen = tgt; }
    } else {
        if (tid == 0) {
            __threadfence();
            *(volatile unsigned*)&g_arr[b] = tgt;
            while (*(volatile unsigned*)&g_gen < tgt) { }
            __threadfence();
        }
        __syncthreads();
    }
}

__device__ __forceinline__ float4 shfl4(float4 v, int m) {
    v.x = __shfl_xor_sync(0xFFFFFFFFu, v.x, m);
    v.y = __shfl_xor_sync(0xFFFFFFFFu, v.y, m);
    v.z = __shfl_xor_sync(0xFFFFFFFFu, v.z, m);
    v.w = __shfl_xor_sync(0xFFFFFFFFu, v.w, m);
    return v;
}
__device__ __forceinline__ float4 add4(float4 a, float4 b) {
    return make_float4(a.x + b.x, a.y + b.y, a.z + b.z, a.w + b.w);
}
__device__ __forceinline__ float4 max4(float4 a, float4 b) {
    return make_float4(fmaxf(a.x, b.x), fmaxf(a.y, b.y),
                       fmaxf(a.z, b.z), fmaxf(a.w, b.w));
}

// ---- separable 3D Gaussian conv (R8-proven) ----
__device__ __forceinline__ void conv3d(float* sa, float* sb,
                                       const float* wx, const float* wyz, int tid) {
    __syncthreads();
    // conv-x: 8 outputs/thread, rolling 8-weight window
    {
        int xg = (tid >> 8) << 3;
        int yz = tid & 255;
        float acc[8] = {0.f,0.f,0.f,0.f,0.f,0.f,0.f,0.f};
        float w[8];
#pragma unroll
        for (int k = 0; k < 8; k++) w[k] = wx[xg + k];
#pragma unroll
        for (int xp = 0; xp < Xd; xp++) {
            float v = sa[(xp << 8) + yz];
#pragma unroll
            for (int k = 0; k < 8; k++) acc[k] += w[k] * v;
            if (xp < Xd - 1) {
#pragma unroll
                for (int k = 7; k >= 1; k--) w[k] = w[k - 1];
                int d = xg - xp - 1; if (d < 0) d = -d;
                w[0] = wx[d];
            }
        }
#pragma unroll
        for (int k = 0; k < 8; k++) sb[((xg + k) << 8) + yz] = acc[k];
    }
    __syncthreads();
    // conv-y: 2 threads/line, warp-uniform half
    {
        int line = tid & 511, half = tid >> 9;
        int z = line & 15, x = line >> 4;
        int base = (x << 8) + z;
        float lin[16], wv[16];
#pragma unroll
        for (int y = 0; y < Yd; y++) lin[y] = sb[base + (y << 4)];
#pragma unroll
        for (int d = 0; d < Yd; d++) wv[d] = wyz[d];
        if (half == 0) {
#pragma unroll
            for (int yo = 0; yo < 8; yo++) {
                float s = 0.f;
#pragma unroll
                for (int yp = 0; yp < Yd; yp++)
                    s += wv[(yo > yp) ? (yo - yp) : (yp - yo)] * lin[yp];
                sa[base + (yo << 4)] = s;
            }
        } else {
#pragma unroll
            for (int yo = 8; yo < 16; yo++) {
                float s = 0.f;
#pragma unroll
                for (int yp = 0; yp < Yd; yp++)
                    s += wv[(yo > yp) ? (yo - yp) : (yp - yo)] * lin[yp];
                sa[base + (yo << 4)] = s;
            }
        }
    }
    __syncthreads();
    // conv-z: 2 threads/line, float4 I/O
    {
        int line = tid & 511, half = tid >> 9;
        float l[16], wv[16];
        const float4* L4 = (const float4*)(sa + line * 16);
#pragma unroll
        for (int i = 0; i < 4; i++) {
            float4 v = L4[i];
            l[4*i] = v.x; l[4*i+1] = v.y; l[4*i+2] = v.z; l[4*i+3] = v.w;
        }
#pragma unroll
        for (int d = 0; d < Yd; d++) wv[d] = wyz[d];
        float o[8];
        if (half == 0) {
#pragma unroll
            for (int zo = 0; zo < 8; zo++) {
                float s = 0.f;
#pragma unroll
                for (int zp = 0; zp < 16; zp++)
                    s += wv[(zo > zp) ? (zo - zp) : (zp - zo)] * l[zp];
                o[zo] = s;
            }
        } else {
#pragma unroll
            for (int zo = 8; zo < 16; zo++) {
                float s = 0.f;
#pragma unroll
                for (int zp = 0; zp < 16; zp++)
                    s += wv[(zo > zp) ? (zo - zp) : (zp - zo)] * l[zp];
                o[zo - 8] = s;
            }
        }
        float4* O4 = (float4*)(sb + line * 16 + half * 8);
        O4[0] = make_float4(o[0], o[1], o[2], o[3]);
        O4[1] = make_float4(o[4], o[5], o[6], o[7]);
    }
    __syncthreads();
}

__global__ __launch_bounds__(1024, 1) void k_crf(
    const float* __restrict__ lu, const float* __restrict__ fp,
    const float* __restrict__ comp, float* __restrict__ out) {
    extern __shared__ float sm[];
    float* s_a   = sm;
    float* s_b   = sm + Nn;
    float* s_wax = sm + 2 * Nn;
    float* s_way = s_wax + 32;
    float* s_wgx = s_way + 16;
    float* s_wgy = s_wgx + 32;
    float* s_cmp = s_wgy + 16;
    __shared__ unsigned s_base;

    int tid = threadIdx.x;
    int b = blockIdx.x;

    if (tid == 0) s_base = *(volatile unsigned*)&g_arr[b];
    if (tid < 32) {
        float d2 = (float)tid * (float)tid;
        s_wax[tid] = __expf(-0.5f * d2 / (ALPHA * ALPHA));
        s_wgx[tid] = __expf(-0.5f * d2 / (GAMMA * GAMMA));
    }
    if (tid < 16) {
        float d2 = (float)tid * (float)tid;
        s_way[tid] = __expf(-0.5f * d2 / (ALPHA * ALPHA));
        s_wgy[tid] = __expf(-0.5f * d2 / (GAMMA * GAMMA));
        s_cmp[tid] = comp[tid];
    }
    __syncthreads();
    unsigned base = s_base, bk = 0;

    // ==== phase A || B ====
    if (b < RK) {
        int i = 0, rr = b;
        while (rr > DEG - i) { rr -= DEG - i + 1; i++; }
        int j = rr;
        float fi = 1.f, fj = 1.f;
        for (int t = 2; t <= i; t++) fi *= (float)t;
        for (int t = 2; t <= j; t++) fj *= (float)t;
        float coef = rsqrtf(fi * fj);
        float ph[8];
#pragma unroll
        for (int u = 0; u < 8; u++) {
            int n = (u << 10) + tid;
            float fa = fp[n] * (1.0f / BETA);
            float fb = fp[Nn + n] * (1.0f / BETA);
            float e = __expf(-0.5f * (fa * fa + fb * fb));
            float pa = 1.f, pb = 1.f;
            for (int t = 0; t < i; t++) pa *= fa;
            for (int t = 0; t < j; t++) pb *= fb;
            ph[u] = coef * pa * pb;
            s_a[n] = ph[u] * e;
        }
        conv3d(s_a, s_b, s_wax, s_way, tid);
#pragma unroll
        for (int u = 0; u < 8; u++) {
            int n = (u << 10) + tid;
            g_part[b][n] = ph[u] * s_b[n];
        }
    } else if (b < RK + 64) {
        if (tid < 128) {
            int n = ((b - RK) << 7) + tid;
            float fa = fp[n] * (1.0f / BETA);
            float fb = fp[Nn + n] * (1.0f / BETA);
            float e = __expf(-0.5f * (fa * fa + fb * fb));
            g_e[n] = e;
            float fi = 1.f, pai = 1.f;
            int r = 0;
#pragma unroll
            for (int i = 0; i <= DEG; i++) {
                if (i > 0) fi *= (float)i;
                float fj = 1.f, pbj = 1.f;
#pragma unroll
                for (int j = 0; j <= DEG - i; j++) {
                    if (j > 0) fj *= (float)j;
                    g_phi[r][n] = rsqrtf(fi * fj) * pai * pbj;
                    pbj *= fb;
                    r++;
                }
                pai *= fa;
            }
            float l0 = lu[n], l1 = lu[Nn + n], l2 = lu[2 * Nn + n], l3 = lu[3 * Nn + n];
            float mx = fmaxf(fmaxf(l0, l1), fmaxf(l2, l3));
            float e0 = __expf(l0 - mx), e1 = __expf(l1 - mx);
            float e2 = __expf(l2 - mx), e3 = __expf(l3 - mx);
            float inv = 1.0f / (e0 + e1 + e2 + e3);
            g_q[0][0][n] = e0 * inv; g_q[0][1][n] = e1 * inv;
            g_q[0][2][n] = e2 * inv; g_q[0][3][n] = e3 * inv;
        }
    }
    gbar(base + (++bk), b, tid);

    // ==== phase C: scales, quad-split (32 blocks x 1024 threads) ====
    if (b < 32) {
        int n = (b << 8) + (tid >> 2);
        int rs = tid & 3;
        float s = 0.f;
#pragma unroll
        for (int k = rs; k < RK; k += 4) s += __ldcg(&g_part[k][n]);
        s += __shfl_xor_sync(0xFFFFFFFFu, s, 1);
        s += __shfl_xor_sync(0xFFFFFFFFu, s, 2);
        float e = g_e[n];
        float pre1v = e * rsqrtf(e * s);
        int x = n >> 8, y = (n >> 4) & 15, z = n & 15;
        float Rx = 0.f, Ry = 0.f, Rz = 0.f;
#pragma unroll
        for (int d = 0; d < Xd; d++) Rx += s_wgx[(x > d) ? (x - d) : (d - x)];
#pragma unroll
        for (int d = 0; d < Yd; d++) {
            Ry += s_wgy[(y > d) ? (y - d) : (d - y)];
            Rz += s_wgy[(z > d) ? (z - d) : (d - z)];
        }
        if (rs == 0) {
            g_pre1[n] = pre1v;
            g_pre2[n] = rsqrtf(Rx * Ry * Rz);
        }
    }
    gbar(base + (++bk), b, tid);

    // ==== phase E: 5 mean-field iterations (psi folded = phi*pre1 on the fly) ====
    int r = b >> 2, c = b & 3;
    bool sp = (r == RK);
    const float4* phi4 = (const float4*)g_phi[sp ? 0 : r];
    const float4* pre4 = sp ? (const float4*)g_pre2 : (const float4*)g_pre1;
    // hoisted update-phase state (blocks 0..63)
    int uc = 0, uks = 0, un4 = 0;
    float4 lun4 = make_float4(0.f, 0.f, 0.f, 0.f);
    float sc0 = 0.f, sc1 = 0.f, sc2 = 0.f, sc3 = 0.f;
    if (b < 64) {
        uc = tid & 3; uks = (tid >> 2) & 7; un4 = (b << 5) + (tid >> 5);
        lun4 = *(const float4*)(lu + uc * Nn + un4 * 4);
        sc0 = s_cmp[uc * 4 + uc];
        sc1 = s_cmp[uc * 4 + (uc ^ 1)];
        sc2 = s_cmp[uc * 4 + (uc ^ 2)];
        sc3 = s_cmp[uc * 4 + (uc ^ 3)];
    }
    for (int it = 0; it < NITER; it++) {
        {
            const float4* q4 = (const float4*)g_q[it & 1][c];
            float4* sa4 = (float4*)s_a;
#pragma unroll
            for (int u = 0; u < 2; u++) {
                int i4 = tid * 2 + u;
                float4 P = pre4[i4];
                float4 M;
                if (sp) M = P;
                else {
                    float4 A = phi4[i4];
                    M = make_float4(A.x * P.x, A.y * P.y, A.z * P.z, A.w * P.w);
                }
                float4 Q = __ldcg(q4 + i4);
                sa4[i4] = make_float4(M.x * Q.x, M.y * Q.y, M.z * Q.z, M.w * Q.w);
            }
            conv3d(s_a, s_b, sp ? s_wgx : s_wax, sp ? s_wgy : s_way, tid);
            const float4* sb4 = (const float4*)s_b;
            float4* dst = (float4*)g_part[b];
#pragma unroll
            for (int u = 0; u < 2; u++) {
                int i4 = tid * 2 + u;
                float4 P = pre4[i4];
                float4 M;
                if (sp) M = P;
                else {
                    float4 A = phi4[i4];
                    M = make_float4(A.x * P.x, A.y * P.y, A.z * P.z, A.w * P.w);
                }
                float4 V = sb4[i4];
                dst[i4] = make_float4(M.x * V.x, M.y * V.y, M.z * V.z, M.w * V.w);
            }
        }
        gbar(base + (++bk), b, tid);
        // ==== update: 64 blocks x 1024 threads, float4-over-n, shuffle reduce ====
        if (b < 64) {
            float4 u = make_float4(0.f, 0.f, 0.f, 0.f);
#pragma unroll
            for (int k = uks; k <= RK; k += 8) {
                float4 p = __ldcg((const float4*)(g_part[k * 4 + uc] + un4 * 4));
                u = add4(u, p);
            }
            u = add4(u, shfl4(u, 4));
            u = add4(u, shfl4(u, 8));
            u = add4(u, shfl4(u, 16));
            float4 v1 = shfl4(u, 1);
            float4 v2 = shfl4(u, 2);
            float4 v3 = shfl4(u, 3);
            float4 qu = make_float4(
                sc0 * u.x + sc1 * v1.x + sc2 * v2.x + sc3 * v3.x,
                sc0 * u.y + sc1 * v1.y + sc2 * v2.y + sc3 * v3.y,
                sc0 * u.z + sc1 * v1.z + sc2 * v2.z + sc3 * v3.z,
                sc0 * u.w + sc1 * v1.w + sc2 * v2.w + sc3 * v3.w);
            float4 lg = make_float4(lun4.x - qu.x, lun4.y - qu.y,
                                    lun4.z - qu.z, lun4.w - qu.w);
            float4 mx = max4(lg, shfl4(lg, 1));
            mx = max4(mx, shfl4(mx, 2));
            float4 e = make_float4(__expf(lg.x - mx.x), __expf(lg.y - mx.y),
                                   __expf(lg.z - mx.z), __expf(lg.w - mx.w));
            float4 ss = add4(e, shfl4(e, 1));
            ss = add4(ss, shfl4(ss, 2));
            float4 qv = make_float4(e.x / ss.x, e.y / ss.y, e.z / ss.z, e.w / ss.w);
            if (uks == 0) {
                float* dstq = (it == NITER - 1) ? (out + uc * Nn)
                                                : (&g_q[(it + 1) & 1][uc][0]);
                *(float4*)(dstq + un4 * 4) = qv;
            }
        }
        if (it < NITER - 1) gbar(base + (++bk), b, tid);
    }
}

extern "C" void kernel_launch(void* const* d_in, const int* in_sizes, int n_in,
                              void* d_out, int out_size) {
    const float* lu   = (const float*)d_in[0];
    const float* fp   = (const float*)d_in[1];
    const float* comp = (const float*)d_in[2];
    float* out = (float*)d_out;

    cudaFuncSetAttribute(k_crf, cudaFuncAttributeMaxDynamicSharedMemorySize, SMEM_BYTES);
    k_crf<<<NBLK, 1024, SMEM_BYTES>>>(lu, fp, comp, out);
}

// round 10
// speedup vs baseline: 1.1881x; 1.1881x over previous
#include <cuda_runtime.h>
#include <math.h>

#define Xd 32
#define Yd 16
#define Nn 8192          // 32*16*16
#define Cc 4
#define NITER 5
#define ALPHA 5.0f
#define BETA  5.0f
#define GAMMA 5.0f
#define DEG 7
#define RK 36            // #(i,j), i+j<=7
#define NBLK (RK * Cc + Cc)   // 148 co-resident blocks
#define SMEM_FLOATS (2 * Nn + 160)
#define SMEM_BYTES (SMEM_FLOATS * 4)

// ---- static device scratch ----
__device__ float g_phi[RK][Nn];      // phi, scaled in place to psi = phi*pre1
__device__ float g_e[Nn];
__device__ float g_pre1[Nn];
__device__ float g_pre2[Nn];
__device__ float g_part[NBLK][Nn];
__device__ float g_q[2][Cc][Nn];
__device__ unsigned g_arr[NBLK];
__device__ unsigned g_gen;

// ---- observer grid barrier (proven) ----
__device__ __forceinline__ void gbar(unsigned tgt, int b, int tid) {
    __syncthreads();
    if (b == 0) {
        if (tid == 0) { __threadfence(); *(volatile unsigned*)&g_arr[0] = tgt; }
        if (tid < NBLK) { while (*(volatile unsigned*)&g_arr[tid] < tgt) { } }
        __syncthreads();
        if (tid == 0) { __threadfence(); *(volatile unsigned*)&g_gen = tgt; }
    } else {
        if (tid == 0) {
            __threadfence();
            *(volatile unsigned*)&g_arr[b] = tgt;
            while (*(volatile unsigned*)&g_gen < tgt) { }
            __threadfence();
        }
        __syncthreads();
    }
}

// ---- separable 3D Gaussian conv (R8-proven, untouched) ----
__device__ __forceinline__ void conv3d(float* sa, float* sb,
                                       const float* wx, const float* wyz, int tid) {
    __syncthreads();
    // conv-x: 8 outputs/thread, rolling 8-weight window
    {
        int xg = (tid >> 8) << 3;
        int yz = tid & 255;
        float acc[8] = {0.f,0.f,0.f,0.f,0.f,0.f,0.f,0.f};
        float w[8];
#pragma unroll
        for (int k = 0; k < 8; k++) w[k] = wx[xg + k];
#pragma unroll
        for (int xp = 0; xp < Xd; xp++) {
            float v = sa[(xp << 8) + yz];
#pragma unroll
            for (int k = 0; k < 8; k++) acc[k] += w[k] * v;
            if (xp < Xd - 1) {
#pragma unroll
                for (int k = 7; k >= 1; k--) w[k] = w[k - 1];
                int d = xg - xp - 1; if (d < 0) d = -d;
                w[0] = wx[d];
            }
        }
#pragma unroll
        for (int k = 0; k < 8; k++) sb[((xg + k) << 8) + yz] = acc[k];
    }
    __syncthreads();
    // conv-y: 2 threads/line, warp-uniform half
    {
        int line = tid & 511, half = tid >> 9;
        int z = line & 15, x = line >> 4;
        int base = (x << 8) + z;
        float lin[16], wv[16];
#pragma unroll
        for (int y = 0; y < Yd; y++) lin[y] = sb[base + (y << 4)];
#pragma unroll
        for (int d = 0; d < Yd; d++) wv[d] = wyz[d];
        if (half == 0) {
#pragma unroll
            for (int yo = 0; yo < 8; yo++) {
                float s = 0.f;
#pragma unroll
                for (int yp = 0; yp < Yd; yp++)
                    s += wv[(yo > yp) ? (yo - yp) : (yp - yo)] * lin[yp];
                sa[base + (yo << 4)] = s;
            }
        } else {
#pragma unroll
            for (int yo = 8; yo < 16; yo++) {
                float s = 0.f;
#pragma unroll
                for (int yp = 0; yp < Yd; yp++)
                    s += wv[(yo > yp) ? (yo - yp) : (yp - yo)] * lin[yp];
                sa[base + (yo << 4)] = s;
            }
        }
    }
    __syncthreads();
    // conv-z: 2 threads/line, float4 I/O
    {
        int line = tid & 511, half = tid >> 9;
        float l[16], wv[16];
        const float4* L4 = (const float4*)(sa + line * 16);
#pragma unroll
        for (int i = 0; i < 4; i++) {
            float4 v = L4[i];
            l[4*i] = v.x; l[4*i+1] = v.y; l[4*i+2] = v.z; l[4*i+3] = v.w;
        }
#pragma unroll
        for (int d = 0; d < Yd; d++) wv[d] = wyz[d];
        float o[8];
        if (half == 0) {
#pragma unroll
            for (int zo = 0; zo < 8; zo++) {
                float s = 0.f;
#pragma unroll
                for (int zp = 0; zp < 16; zp++)
                    s += wv[(zo > zp) ? (zo - zp) : (zp - zo)] * l[zp];
                o[zo] = s;
            }
        } else {
#pragma unroll
            for (int zo = 8; zo < 16; zo++) {
                float s = 0.f;
#pragma unroll
                for (int zp = 0; zp < 16; zp++)
                    s += wv[(zo > zp) ? (zo - zp) : (zp - zo)] * l[zp];
                o[zo - 8] = s;
            }
        }
        float4* O4 = (float4*)(sb + line * 16 + half * 8);
        O4[0] = make_float4(o[0], o[1], o[2], o[3]);
        O4[1] = make_float4(o[4], o[5], o[6], o[7]);
    }
    __syncthreads();
}

__global__ __launch_bounds__(1024, 1) void k_crf(
    const float* __restrict__ lu, const float* __restrict__ fp,
    const float* __restrict__ comp, float* __restrict__ out) {
    extern __shared__ float sm[];
    float* s_a   = sm;
    float* s_b   = sm + Nn;
    float* s_wax = sm + 2 * Nn;
    float* s_way = s_wax + 32;
    float* s_wgx = s_way + 16;
    float* s_wgy = s_wgx + 32;
    float* s_cmp = s_wgy + 16;
    __shared__ unsigned s_base;

    int tid = threadIdx.x;
    int b = blockIdx.x;

    if (tid == 0) s_base = *(volatile unsigned*)&g_arr[b];
    if (tid < 32) {
        float d2 = (float)tid * (float)tid;
        s_wax[tid] = __expf(-0.5f * d2 / (ALPHA * ALPHA));
        s_wgx[tid] = __expf(-0.5f * d2 / (GAMMA * GAMMA));
    }
    if (tid < 16) {
        float d2 = (float)tid * (float)tid;
        s_way[tid] = __expf(-0.5f * d2 / (ALPHA * ALPHA));
        s_wgy[tid] = __expf(-0.5f * d2 / (GAMMA * GAMMA));
        s_cmp[tid] = comp[tid];
    }
    __syncthreads();
    unsigned base = s_base, bk = 0;

    // ==== phase A || B ====
    if (b < RK) {
        int i = 0, rr = b;
        while (rr > DEG - i) { rr -= DEG - i + 1; i++; }
        int j = rr;
        float fi = 1.f, fj = 1.f;
        for (int t = 2; t <= i; t++) fi *= (float)t;
        for (int t = 2; t <= j; t++) fj *= (float)t;
        float coef = rsqrtf(fi * fj);
        float ph[8];
#pragma unroll
        for (int u = 0; u < 8; u++) {
            int n = (u << 10) + tid;
            float fa = fp[n] * (1.0f / BETA);
            float fb = fp[Nn + n] * (1.0f / BETA);
            float e = __expf(-0.5f * (fa * fa + fb * fb));
            float pa = 1.f, pb = 1.f;
            for (int t = 0; t < i; t++) pa *= fa;
            for (int t = 0; t < j; t++) pb *= fb;
            ph[u] = coef * pa * pb;
            s_a[n] = ph[u] * e;
        }
        conv3d(s_a, s_b, s_wax, s_way, tid);
#pragma unroll
        for (int u = 0; u < 8; u++) {
            int n = (u << 10) + tid;
            g_part[b][n] = ph[u] * s_b[n];
        }
    } else if (b < RK + 64) {
        if (tid < 128) {
            int n = ((b - RK) << 7) + tid;
            float fa = fp[n] * (1.0f / BETA);
            float fb = fp[Nn + n] * (1.0f / BETA);
            float e = __expf(-0.5f * (fa * fa + fb * fb));
            g_e[n] = e;
            float fi = 1.f, pai = 1.f;
            int r = 0;
#pragma unroll
            for (int i = 0; i <= DEG; i++) {
                if (i > 0) fi *= (float)i;
                float fj = 1.f, pbj = 1.f;
#pragma unroll
                for (int j = 0; j <= DEG - i; j++) {
                    if (j > 0) fj *= (float)j;
                    g_phi[r][n] = rsqrtf(fi * fj) * pai * pbj;
                    pbj *= fb;
                    r++;
                }
                pai *= fa;
            }
            float l0 = lu[n], l1 = lu[Nn + n], l2 = lu[2 * Nn + n], l3 = lu[3 * Nn + n];
            float mx = fmaxf(fmaxf(l0, l1), fmaxf(l2, l3));
            float e0 = __expf(l0 - mx), e1 = __expf(l1 - mx);
            float e2 = __expf(l2 - mx), e3 = __expf(l3 - mx);
            float inv = 1.0f / (e0 + e1 + e2 + e3);
            g_q[0][0][n] = e0 * inv; g_q[0][1][n] = e1 * inv;
            g_q[0][2][n] = e2 * inv; g_q[0][3][n] = e3 * inv;
        }
    }
    gbar(base + (++bk), b, tid);

    // ==== phase C: normalization scales (R8 version) ====
    if (b < 32 && tid < 256) {
        int n = (b << 8) + tid;
        float s = 0.f;
#pragma unroll
        for (int r = 0; r < RK; r++) s += __ldcg(&g_part[r][n]);
        float e = g_e[n];
        g_pre1[n] = e * rsqrtf(e * s);
        int x = n >> 8, y = (n >> 4) & 15, z = n & 15;
        float Rx = 0.f, Ry = 0.f, Rz = 0.f;
#pragma unroll
        for (int d = 0; d < Xd; d++) Rx += s_wgx[(x > d) ? (x - d) : (d - x)];
#pragma unroll
        for (int d = 0; d < Yd; d++) {
            Ry += s_wgy[(y > d) ? (y - d) : (d - y)];
            Rz += s_wgy[(z > d) ? (z - d) : (d - z)];
        }
        g_pre2[n] = rsqrtf(Rx * Ry * Rz);
    }
    gbar(base + (++bk), b, tid);

    // ==== phase D: psi = phi * pre1 in place (R8 version) ====
    if (b < RK) {
#pragma unroll
        for (int u = 0; u < 8; u++) {
            int n = (u << 10) + tid;
            g_phi[b][n] *= g_pre1[n];
        }
    }
    gbar(base + (++bk), b, tid);

    // ==== phase E: 5 mean-field iterations ====
    int r = b >> 2, c = b & 3;
    bool sp = (r == RK);
    const float4* mul4 = sp ? (const float4*)g_pre2 : (const float4*)g_phi[r];
    const float* wxE = sp ? s_wgx : s_wax;
    const float* wyE = sp ? s_wgy : s_way;
    // hoisted update-phase state: 32 blocks x 1024 threads, warp-per-channel
    // c = warp&3, n = b*256 + (warp>>2)*32 + lane  -> k-loads are warp-coalesced
    int uc = 0, un = 0, ulv = 0;
    float lu0 = 0.f, lu1 = 0.f, lu2 = 0.f, lu3 = 0.f;
    if (b < 32) {
        int warp = tid >> 5, lane = tid & 31;
        uc = warp & 3;
        ulv = ((warp >> 2) << 5) + lane;      // local voxel 0..255
        un = (b << 8) + ulv;
        lu0 = lu[un]; lu1 = lu[Nn + un]; lu2 = lu[2 * Nn + un]; lu3 = lu[3 * Nn + un];
    }
    for (int it = 0; it < NITER; it++) {
        {
            const float4* q4 = (const float4*)g_q[it & 1][c];
            float4* sa4 = (float4*)s_a;
#pragma unroll
            for (int u = 0; u < 2; u++) {
                int i4 = tid * 2 + u;
                float4 M = mul4[i4];          // immutable after phase D
                float4 Q = __ldcg(q4 + i4);   // mutable: L2-coherent
                sa4[i4] = make_float4(M.x * Q.x, M.y * Q.y, M.z * Q.z, M.w * Q.w);
            }
            conv3d(s_a, s_b, wxE, wyE, tid);
            const float4* sb4 = (const float4*)s_b;
            float4* dst = (float4*)g_part[b];
#pragma unroll
            for (int u = 0; u < 2; u++) {
                int i4 = tid * 2 + u;
                float4 M = mul4[i4];
                float4 V = sb4[i4];
                dst[i4] = make_float4(M.x * V.x, M.y * V.y, M.z * V.z, M.w * V.w);
            }
        }
        gbar(base + (++bk), b, tid);
        // ==== update: 32 blocks, warp-coalesced k-sweep + smem channel exchange ====
        if (b < 32) {
            float u = 0.f;
#pragma unroll
            for (int k = 0; k <= RK; k++)
                u += __ldcg(&g_part[k * 4 + uc][un]);
            s_a[uc * 256 + ulv] = u;          // conflict-free: lanes -> consecutive
            __syncthreads();
            float u0 = s_a[0 * 256 + ulv], u1 = s_a[1 * 256 + ulv];
            float u2 = s_a[2 * 256 + ulv], u3 = s_a[3 * 256 + ulv];
            float lg0 = lu0 - (s_cmp[0] * u0 + s_cmp[1] * u1 + s_cmp[2] * u2 + s_cmp[3] * u3);
            float lg1 = lu1 - (s_cmp[4] * u0 + s_cmp[5] * u1 + s_cmp[6] * u2 + s_cmp[7] * u3);
            float lg2 = lu2 - (s_cmp[8] * u0 + s_cmp[9] * u1 + s_cmp[10] * u2 + s_cmp[11] * u3);
            float lg3 = lu3 - (s_cmp[12] * u0 + s_cmp[13] * u1 + s_cmp[14] * u2 + s_cmp[15] * u3);
            float mx = fmaxf(fmaxf(lg0, lg1), fmaxf(lg2, lg3));
            float e0 = __expf(lg0 - mx), e1 = __expf(lg1 - mx);
            float e2 = __expf(lg2 - mx), e3 = __expf(lg3 - mx);
            float inv = 1.0f / (e0 + e1 + e2 + e3);
            float qv = (uc == 0 ? e0 : uc == 1 ? e1 : uc == 2 ? e2 : e3) * inv;
            if (it == NITER - 1) out[uc * Nn + un] = qv;
            else                 g_q[(it + 1) & 1][uc][un] = qv;
        }
        if (it < NITER - 1) gbar(base + (++bk), b, tid);
    }
}

extern "C" void kernel_launch(void* const* d_in, const int* in_sizes, int n_in,
                              void* d_out, int out_size) {
    const float* lu   = (const float*)d_in[0];
    const float* fp   = (const float*)d_in[1];
    const float* comp = (const float*)d_in[2];
    float* out = (float*)d_out;

    cudaFuncSetAttribute(k_crf, cudaFuncAttributeMaxDynamicSharedMemorySize, SMEM_BYTES);
    k_crf<<<NBLK, 1024, SMEM_BYTES>>>(lu, fp, comp, out);
}